// round 2
// baseline (speedup 1.0000x reference)
#include <cuda_runtime.h>
#include <cuda_bf16.h>
#include <cstddef>

// SkipGram negative-sampling loss.
// Inputs (metadata order): pos_w[int32,B], pos_v[int32,B], neg_v[int32,B*5],
//                          w_table[f32,V*128], v_table[f32,V*128]
// Output: float scalar loss = -(sum logsig(w·v) + sum_k logsig(-(nk·v)))

#define DIM 128
#define NEG 5
#define WARPS_PER_BLOCK 8
#define THREADS (WARPS_PER_BLOCK * 32)

__global__ void zero_out_kernel(float* out) { *out = 0.0f; }

__device__ __forceinline__ float log_sigmoid(float x) {
    // stable: min(x,0) - log1p(exp(-|x|))
    return fminf(x, 0.0f) - log1pf(expf(-fabsf(x)));
}

__global__ __launch_bounds__(THREADS) void skipgram_loss_kernel(
    const int* __restrict__ pos_w,
    const int* __restrict__ pos_v,
    const int* __restrict__ neg_v,
    const float* __restrict__ w_table,
    const float* __restrict__ v_table,
    float* __restrict__ out,
    int batch)
{
    const int lane = threadIdx.x & 31;
    const int warp_in_block = threadIdx.x >> 5;
    const int b = blockIdx.x * WARPS_PER_BLOCK + warp_in_block;

    float local = 0.0f;

    if (b < batch) {
        // Gather indices (uniform across warp; UR path)
        const int iw = __ldg(pos_w + b);
        const int iv = __ldg(pos_v + b);
        int in[NEG];
#pragma unroll
        for (int k = 0; k < NEG; k++) in[k] = __ldg(neg_v + (size_t)b * NEG + k);

        // Row pointers: each row is 128 floats = 512B, lane l takes float4 #l.
        const float4* wrow = reinterpret_cast<const float4*>(w_table + (size_t)iw * DIM);
        const float4* vrow = reinterpret_cast<const float4*>(v_table + (size_t)iv * DIM);

        // Issue all 7 loads up front for maximum MLP.
        float4 w4 = __ldg(wrow + lane);
        float4 v4 = __ldg(vrow + lane);
        float4 n4[NEG];
#pragma unroll
        for (int k = 0; k < NEG; k++) {
            const float4* nrow = reinterpret_cast<const float4*>(v_table + (size_t)in[k] * DIM);
            n4[k] = __ldg(nrow + lane);
        }

        // Per-lane partial dots.
        float dp = w4.x * v4.x + w4.y * v4.y + w4.z * v4.z + w4.w * v4.w;
        float dn[NEG];
#pragma unroll
        for (int k = 0; k < NEG; k++)
            dn[k] = n4[k].x * v4.x + n4[k].y * v4.y + n4[k].z * v4.z + n4[k].w * v4.w;

        // Butterfly-reduce 6 scalars across the warp.
#pragma unroll
        for (int off = 16; off > 0; off >>= 1) {
            dp += __shfl_xor_sync(0xFFFFFFFFu, dp, off);
#pragma unroll
            for (int k = 0; k < NEG; k++)
                dn[k] += __shfl_xor_sync(0xFFFFFFFFu, dn[k], off);
        }

        if (lane == 0) {
            float s = log_sigmoid(dp);
#pragma unroll
            for (int k = 0; k < NEG; k++) s += log_sigmoid(-dn[k]);
            local = s;
        }
    }

    // Block reduce (one value per warp, lane 0 holds it).
    __shared__ float warp_sums[WARPS_PER_BLOCK];
    if (lane == 0) warp_sums[warp_in_block] = local;
    __syncthreads();

    if (threadIdx.x == 0) {
        float bs = 0.0f;
#pragma unroll
        for (int i = 0; i < WARPS_PER_BLOCK; i++) bs += warp_sums[i];
        // loss = -(sum of logsigmoids)
        atomicAdd(out, -bs);
    }
}

extern "C" void kernel_launch(void* const* d_in, const int* in_sizes, int n_in,
                              void* d_out, int out_size)
{
    const int*   pos_w   = (const int*)d_in[0];
    const int*   pos_v   = (const int*)d_in[1];
    const int*   neg_v   = (const int*)d_in[2];
    const float* w_table = (const float*)d_in[3];
    const float* v_table = (const float*)d_in[4];
    float* out = (float*)d_out;

    const int batch = in_sizes[0];

    zero_out_kernel<<<1, 1>>>(out);

    const int blocks = (batch + WARPS_PER_BLOCK - 1) / WARPS_PER_BLOCK;
    skipgram_loss_kernel<<<blocks, THREADS>>>(pos_w, pos_v, neg_v,
                                              w_table, v_table, out, batch);
}

// round 3
// speedup vs baseline: 1.0370x; 1.0370x over previous
#include <cuda_runtime.h>
#include <cuda_bf16.h>
#include <cstddef>

// SkipGram negative-sampling loss.
// Inputs (metadata order): pos_w[int32,B], pos_v[int32,B], neg_v[int32,B*5],
//                          w_table[f32,V*128], v_table[f32,V*128]
// Output: float scalar loss = -(sum logsig(w·v) + sum_k logsig(-(nk·v)))

#define DIM 128
#define NEG 5
#define WARPS_PER_BLOCK 8
#define THREADS (WARPS_PER_BLOCK * 32)

__global__ void zero_out_kernel(float* out) { *out = 0.0f; }

__device__ __forceinline__ float log_sigmoid_fast(float x) {
    // stable: min(x,0) - log1p(exp(-|x|)); fast intrinsics (tolerance is 1e-3,
    // current rel_err 5e-5, and only 6 evals per 32-lane warp).
    float e = __expf(-fabsf(x));
    return fminf(x, 0.0f) - __logf(1.0f + e);
}

__global__ __launch_bounds__(THREADS, 8) void skipgram_loss_kernel(
    const int* __restrict__ pos_w,
    const int* __restrict__ pos_v,
    const int* __restrict__ neg_v,
    const float* __restrict__ w_table,
    const float* __restrict__ v_table,
    float* __restrict__ out,
    int batch)
{
    const int lane = threadIdx.x & 31;
    const int warp_in_block = threadIdx.x >> 5;
    const int b = blockIdx.x * WARPS_PER_BLOCK + warp_in_block;

    float local = 0.0f;

    if (b < batch) {
        // Gather indices (warp-uniform).
        const int iw = __ldg(pos_w + b);
        const int iv = __ldg(pos_v + b);
        int in[NEG];
#pragma unroll
        for (int k = 0; k < NEG; k++) in[k] = __ldg(neg_v + b * NEG + k);

        // 32-bit float4-granule offsets: idx*32 + lane < 2^25, well within u32.
        // Each row = 128 floats = 32 float4 = 512B; lane l takes granule l.
        const float4* wt4 = reinterpret_cast<const float4*>(w_table);
        const float4* vt4 = reinterpret_cast<const float4*>(v_table);
        const unsigned uw = (unsigned)iw * 32u + (unsigned)lane;
        const unsigned uv = (unsigned)iv * 32u + (unsigned)lane;
        unsigned un[NEG];
#pragma unroll
        for (int k = 0; k < NEG; k++) un[k] = (unsigned)in[k] * 32u + (unsigned)lane;

        // Issue all 7 row loads up front (front-batched MLP).
        float4 v4 = __ldg(vt4 + uv);
        float4 w4 = __ldg(wt4 + uw);
        float4 n4[NEG];
#pragma unroll
        for (int k = 0; k < NEG; k++) n4[k] = __ldg(vt4 + un[k]);

        // Per-lane partial dots.
        float dp = w4.x * v4.x + w4.y * v4.y + w4.z * v4.z + w4.w * v4.w;
        float dn[NEG];
#pragma unroll
        for (int k = 0; k < NEG; k++)
            dn[k] = n4[k].x * v4.x + n4[k].y * v4.y + n4[k].z * v4.z + n4[k].w * v4.w;

        // Butterfly-reduce the 6 scalars across the warp.
#pragma unroll
        for (int off = 16; off > 0; off >>= 1) {
            dp += __shfl_xor_sync(0xFFFFFFFFu, dp, off);
#pragma unroll
            for (int k = 0; k < NEG; k++)
                dn[k] += __shfl_xor_sync(0xFFFFFFFFu, dn[k], off);
        }

        if (lane == 0) {
            float s = log_sigmoid_fast(dp);
#pragma unroll
            for (int k = 0; k < NEG; k++) s += log_sigmoid_fast(-dn[k]);
            local = s;
        }
    }

    // Block reduce (one value per warp, lane 0 holds it) -> one atomic per CTA.
    __shared__ float warp_sums[WARPS_PER_BLOCK];
    if (lane == 0) warp_sums[warp_in_block] = local;
    __syncthreads();

    if (threadIdx.x == 0) {
        float bs = 0.0f;
#pragma unroll
        for (int i = 0; i < WARPS_PER_BLOCK; i++) bs += warp_sums[i];
        atomicAdd(out, -bs);   // loss = -(sum of logsigmoids)
    }
}

extern "C" void kernel_launch(void* const* d_in, const int* in_sizes, int n_in,
                              void* d_out, int out_size)
{
    const int*   pos_w   = (const int*)d_in[0];
    const int*   pos_v   = (const int*)d_in[1];
    const int*   neg_v   = (const int*)d_in[2];
    const float* w_table = (const float*)d_in[3];
    const float* v_table = (const float*)d_in[4];
    float* out = (float*)d_out;

    const int batch = in_sizes[0];

    zero_out_kernel<<<1, 1>>>(out);

    const int blocks = (batch + WARPS_PER_BLOCK - 1) / WARPS_PER_BLOCK;
    skipgram_loss_kernel<<<blocks, THREADS>>>(pos_w, pos_v, neg_v,
                                              w_table, v_table, out, batch);
}